// round 2
// baseline (speedup 1.0000x reference)
#include <cuda_runtime.h>
#include <cuda_fp16.h>
#include <cstdint>

#define M_DIM 8192
#define N_DIM 4096
#define K_DIM 4096

#define BM 128
#define BN 128
#define BK 32
#define STAGES 3
#define KT (K_DIM / BK)

// Scratch (static device allocations are allowed; cudaMalloc is not)
__device__ __half g_xh[(size_t)M_DIM * K_DIM];   // 64 MB: x in fp16
__device__ __half g_ws[(size_t)N_DIM * K_DIM];   // 32 MB: ternary sign pattern in fp16
__device__ float  g_absum;

__global__ void zero_sum_kernel() { g_absum = 0.0f; }

__global__ void abs_sum_kernel(const float* __restrict__ w) {
    const int n4 = (N_DIM * K_DIM) / 4;
    float s = 0.f;
    const float4* w4 = (const float4*)w;
    for (int j = blockIdx.x * blockDim.x + threadIdx.x; j < n4; j += gridDim.x * blockDim.x) {
        float4 v = w4[j];
        s += fabsf(v.x) + fabsf(v.y) + fabsf(v.z) + fabsf(v.w);
    }
#pragma unroll
    for (int o = 16; o; o >>= 1) s += __shfl_xor_sync(0xffffffffu, s, o);
    __shared__ float red[8];
    int lane = threadIdx.x & 31, wid = threadIdx.x >> 5;
    if (lane == 0) red[wid] = s;
    __syncthreads();
    if (wid == 0) {
        s = (lane < 8) ? red[lane] : 0.f;
#pragma unroll
        for (int o = 4; o; o >>= 1) s += __shfl_xor_sync(0xffffffffu, s, o);
        if (lane == 0) atomicAdd(&g_absum, s);
    }
}

__global__ void quantize_w_kernel(const float* __restrict__ w) {
    const float t = 0.5f * g_absum * (1.0f / ((float)N_DIM * (float)K_DIM));
    size_t i = ((size_t)blockIdx.x * blockDim.x + threadIdx.x) * 8;
    float4 v0 = *(const float4*)(w + i);
    float4 v1 = *(const float4*)(w + i + 4);
    float f[8] = {v0.x, v0.y, v0.z, v0.w, v1.x, v1.y, v1.z, v1.w};
    __half h[8];
#pragma unroll
    for (int j = 0; j < 8; ++j)
        h[j] = __float2half_rn(f[j] > t ? 1.0f : (f[j] < -t ? -1.0f : 0.0f));
    *(uint4*)(g_ws + i) = *(const uint4*)h;
}

__global__ void convert_x_kernel(const float* __restrict__ x) {
    size_t i = ((size_t)blockIdx.x * blockDim.x + threadIdx.x) * 8;
    float4 v0 = *(const float4*)(x + i);
    float4 v1 = *(const float4*)(x + i + 4);
    float f[8] = {v0.x, v0.y, v0.z, v0.w, v1.x, v1.y, v1.z, v1.w};
    __half h[8];
#pragma unroll
    for (int j = 0; j < 8; ++j) h[j] = __float2half_rn(f[j]);
    *(uint4*)(g_xh + i) = *(const uint4*)h;
}

__device__ __forceinline__ uint32_t smem_u32(const void* p) {
    return (uint32_t)__cvta_generic_to_shared(p);
}

__global__ __launch_bounds__(256, 2) void ternary_gemm_kernel(float* __restrict__ out) {
    // 48 KB static shared: 3 stages x (128x32 A + 128x32 B) fp16
    __shared__ __half As[STAGES][BM * BK];
    __shared__ __half Bs[STAGES][BN * BK];

    const int tid  = threadIdx.x;
    const int lane = tid & 31;
    const int warp = tid >> 5;
    const int wm = warp & 1;    // 2 warps along M (64 rows each)
    const int wn = warp >> 1;   // 4 warps along N (32 cols each)
    const int bm = blockIdx.y * BM;
    const int bn = blockIdx.x * BN;

    const __half* A = g_xh;
    const __half* B = g_ws;

    float acc[4][4][4];
#pragma unroll
    for (int i = 0; i < 4; ++i)
#pragma unroll
        for (int j = 0; j < 4; ++j)
#pragma unroll
            for (int k = 0; k < 4; ++k) acc[i][j][k] = 0.f;

    // per-thread cp.async coords: chunk = tid and tid+256 of 512 (row = chunk/4, 16B col chunk = chunk%4)
    const int r0 = tid >> 2;
    const int c0 = tid & 3;
    const int swc = (c0 ^ (r0 & 3)) * 16;   // xor swizzle, same for row r0 and r0+64

    auto issue_stage = [&](int kt) {
        const int stage = kt % STAGES;
        const __half* ga  = A + (size_t)(bm + r0) * K_DIM + kt * BK + c0 * 8;
        const __half* gb  = B + (size_t)(bn + r0) * K_DIM + kt * BK + c0 * 8;
        uint32_t sa = smem_u32(&As[stage][0]) + r0 * 64 + swc;
        uint32_t sb = smem_u32(&Bs[stage][0]) + r0 * 64 + swc;
        asm volatile("cp.async.ca.shared.global [%0], [%1], 16;" :: "r"(sa), "l"(ga));
        asm volatile("cp.async.ca.shared.global [%0], [%1], 16;" :: "r"(sa + 4096), "l"(ga + (size_t)64 * K_DIM));
        asm volatile("cp.async.ca.shared.global [%0], [%1], 16;" :: "r"(sb), "l"(gb));
        asm volatile("cp.async.ca.shared.global [%0], [%1], 16;" :: "r"(sb + 4096), "l"(gb + (size_t)64 * K_DIM));
        asm volatile("cp.async.commit_group;");
    };

    auto compute_stage = [&](int stage) {
        const uint32_t abase = smem_u32(&As[stage][0]);
        const uint32_t bbase = smem_u32(&Bs[stage][0]);
#pragma unroll
        for (int ks = 0; ks < 2; ++ks) {
            uint32_t a[4][4];
            uint32_t b[4][2];
            {
                const int chunkoff = ks * 2 + (lane >> 4);
#pragma unroll
                for (int mt = 0; mt < 4; ++mt) {
                    const int rr = wm * 64 + mt * 16 + (lane & 15);
                    const uint32_t addr = abase + rr * 64 + ((chunkoff ^ (rr & 3)) << 4);
                    asm volatile("ldmatrix.sync.aligned.m8n8.x4.shared.b16 {%0,%1,%2,%3}, [%4];"
                                 : "=r"(a[mt][0]), "=r"(a[mt][1]), "=r"(a[mt][2]), "=r"(a[mt][3])
                                 : "r"(addr));
                }
            }
            {
                const int l = lane & 15;
                const int chunkoff = ks * 2 + (l >> 3);
#pragma unroll
                for (int nt = 0; nt < 4; ++nt) {
                    const int rr = wn * 32 + nt * 8 + (l & 7);
                    const uint32_t addr = bbase + rr * 64 + ((chunkoff ^ (rr & 3)) << 4);
                    asm volatile("ldmatrix.sync.aligned.m8n8.x2.shared.b16 {%0,%1}, [%2];"
                                 : "=r"(b[nt][0]), "=r"(b[nt][1]) : "r"(addr));
                }
            }
#pragma unroll
            for (int mt = 0; mt < 4; ++mt)
#pragma unroll
                for (int nt = 0; nt < 4; ++nt)
                    asm volatile("mma.sync.aligned.m16n8k16.row.col.f32.f16.f16.f32 "
                                 "{%0,%1,%2,%3}, {%4,%5,%6,%7}, {%8,%9}, {%0,%1,%2,%3};"
                                 : "+f"(acc[mt][nt][0]), "+f"(acc[mt][nt][1]),
                                   "+f"(acc[mt][nt][2]), "+f"(acc[mt][nt][3])
                                 : "r"(a[mt][0]), "r"(a[mt][1]), "r"(a[mt][2]), "r"(a[mt][3]),
                                   "r"(b[nt][0]), "r"(b[nt][1]));
        }
    };

    int kf = 0;
    for (; kf < STAGES - 1; ++kf) issue_stage(kf);
    asm volatile("cp.async.wait_group %0;" :: "n"(STAGES - 2));
    __syncthreads();

    for (int kt = 0; kt < KT; ++kt) {
        if (kf < KT) { issue_stage(kf); ++kf; }
        compute_stage(kt % STAGES);
        asm volatile("cp.async.wait_group %0;" :: "n"(STAGES - 2));
        __syncthreads();
    }

    const float alpha = g_absum * (1.0f / ((float)N_DIM * (float)K_DIM));
    const int mrow = bm + wm * 64 + (lane >> 2);
    const int ncol = bn + wn * 32 + (lane & 3) * 2;
#pragma unroll
    for (int mt = 0; mt < 4; ++mt) {
#pragma unroll
        for (int nt = 0; nt < 4; ++nt) {
            float2 v0 = make_float2(alpha * acc[mt][nt][0], alpha * acc[mt][nt][1]);
            float2 v1 = make_float2(alpha * acc[mt][nt][2], alpha * acc[mt][nt][3]);
            size_t base0 = (size_t)(mrow + mt * 16) * N_DIM + (ncol + nt * 8);
            size_t base1 = base0 + (size_t)8 * N_DIM;
            *(float2*)(out + base0) = v0;
            *(float2*)(out + base1) = v1;
        }
    }
}

extern "C" void kernel_launch(void* const* d_in, const int* in_sizes, int n_in,
                              void* d_out, int out_size) {
    const float* x = (const float*)d_in[0];
    const float* w = (const float*)d_in[1];
    if (n_in >= 2 && in_sizes[0] < in_sizes[1]) {  // defensive: x is the bigger tensor
        const float* t = x; x = w; w = t;
    }
    float* out = (float*)d_out;

    zero_sum_kernel<<<1, 1>>>();
    abs_sum_kernel<<<2048, 256>>>(w);
    quantize_w_kernel<<<(N_DIM * (size_t)K_DIM / 8) / 256, 256>>>(w);
    convert_x_kernel<<<((size_t)M_DIM * K_DIM / 8) / 256, 256>>>(x);

    dim3 grid(N_DIM / BN, M_DIM / BM);
    ternary_gemm_kernel<<<grid, 256>>>(out);
}

// round 5
// speedup vs baseline: 1.7380x; 1.7380x over previous
#include <cuda_runtime.h>
#include <cuda_fp16.h>
#include <cstdint>

#define M_DIM 8192
#define N_DIM 4096
#define K_DIM 4096

#define BM 128
#define BN 256
#define BK 64
#define STAGES 3
#define KTILES (K_DIM / BK)

// per-stage smem: A 128x64 f16 (16KB) + B 256x64 f16 (32KB) = 48KB; 3 stages = 144KB
#define STAGE_BYTES 49152
#define B_REL 16384
#define SMEM_TOTAL (STAGES * STAGE_BYTES)

// Scratch (static device arrays: allowed; cudaMalloc: not)
__device__ __half g_xh[(size_t)M_DIM * K_DIM];   // 64 MB: x in fp16
__device__ __half g_ws[(size_t)N_DIM * K_DIM];   // 32 MB: ternary sign pattern in fp16
__device__ float  g_absum;

// ---------------- prep kernels ----------------

__global__ void zero_sum_kernel() { g_absum = 0.0f; }

__global__ void abs_sum_kernel(const float* __restrict__ w) {
    const int n4 = (N_DIM * K_DIM) / 4;
    float s = 0.f;
    const float4* w4 = (const float4*)w;
    for (int j = blockIdx.x * blockDim.x + threadIdx.x; j < n4; j += gridDim.x * blockDim.x) {
        float4 v = w4[j];
        s += fabsf(v.x) + fabsf(v.y) + fabsf(v.z) + fabsf(v.w);
    }
#pragma unroll
    for (int o = 16; o; o >>= 1) s += __shfl_xor_sync(0xffffffffu, s, o);
    __shared__ float red[8];
    int lane = threadIdx.x & 31, wid = threadIdx.x >> 5;
    if (lane == 0) red[wid] = s;
    __syncthreads();
    if (wid == 0) {
        s = (lane < 8) ? red[lane] : 0.f;
#pragma unroll
        for (int o = 4; o; o >>= 1) s += __shfl_xor_sync(0xffffffffu, s, o);
        if (lane == 0) atomicAdd(&g_absum, s);
    }
}

__global__ void quantize_w_kernel(const float* __restrict__ w) {
    const float t = 0.5f * g_absum * (1.0f / ((float)N_DIM * (float)K_DIM));
    size_t i = ((size_t)blockIdx.x * blockDim.x + threadIdx.x) * 8;
    float4 v0 = *(const float4*)(w + i);
    float4 v1 = *(const float4*)(w + i + 4);
    float f[8] = {v0.x, v0.y, v0.z, v0.w, v1.x, v1.y, v1.z, v1.w};
    __half h[8];
#pragma unroll
    for (int j = 0; j < 8; ++j)
        h[j] = __float2half_rn(f[j] > t ? 1.0f : (f[j] < -t ? -1.0f : 0.0f));
    *(uint4*)(g_ws + i) = *(const uint4*)h;
}

__global__ void convert_x_kernel(const float* __restrict__ x) {
    size_t i = ((size_t)blockIdx.x * blockDim.x + threadIdx.x) * 8;
    float4 v0 = *(const float4*)(x + i);
    float4 v1 = *(const float4*)(x + i + 4);
    float f[8] = {v0.x, v0.y, v0.z, v0.w, v1.x, v1.y, v1.z, v1.w};
    __half h[8];
#pragma unroll
    for (int j = 0; j < 8; ++j) h[j] = __float2half_rn(f[j]);
    *(uint4*)(g_xh + i) = *(const uint4*)h;
}

// ---------------- GEMM ----------------

__device__ __forceinline__ uint32_t smem_u32(const void* p) {
    return (uint32_t)__cvta_generic_to_shared(p);
}

__global__ __launch_bounds__(256, 1) void ternary_gemm_kernel(float* __restrict__ out) {
    extern __shared__ char smem[];
    const uint32_t sbase = smem_u32(smem);

    const int tid  = threadIdx.x;
    const int lane = tid & 31;
    const int warp = tid >> 5;
    const int wm = warp >> 2;          // 2 warps along M (64 rows each)
    const int wn = warp & 3;           // 4 warps along N (64 cols each)
    const int bm = blockIdx.y * BM;
    const int bn = blockIdx.x * BN;

    float acc[4][8][4];
#pragma unroll
    for (int i = 0; i < 4; ++i)
#pragma unroll
        for (int j = 0; j < 8; ++j)
#pragma unroll
            for (int k = 0; k < 4; ++k) acc[i][j][k] = 0.f;

    // cp.async mapping: each thread: A 4 chunks, B 8 chunks (16B each, 128B rows, xor-8 swizzle)
    auto load_tile = [&](int kt) {
        const uint32_t abase = sbase + (kt % STAGES) * STAGE_BYTES;
        const uint32_t bbase = abase + B_REL;
        const __half* gA = g_xh + (size_t)bm * K_DIM + (size_t)kt * BK;
        const __half* gB = g_ws + (size_t)bn * K_DIM + (size_t)kt * BK;
#pragma unroll
        for (int i = 0; i < 4; ++i) {
            const int idx = tid + i * 256;            // 0..1023
            const int r = idx >> 3;                   // A row 0..127
            const int c = idx & 7;
            const uint32_t sw = ((uint32_t)((c ^ r) & 7)) << 4;
            asm volatile("cp.async.cg.shared.global [%0], [%1], 16;"
                         :: "r"(abase + r * 128 + sw),
                            "l"((const char*)(gA + (size_t)r * K_DIM) + c * 16));
        }
#pragma unroll
        for (int i = 0; i < 8; ++i) {
            const int idx = tid + i * 256;            // 0..2047
            const int r = idx >> 3;                   // B row 0..255
            const int c = idx & 7;
            const uint32_t sw = ((uint32_t)((c ^ r) & 7)) << 4;
            asm volatile("cp.async.cg.shared.global [%0], [%1], 16;"
                         :: "r"(bbase + r * 128 + sw),
                            "l"((const char*)(gB + (size_t)r * K_DIM) + c * 16));
        }
        asm volatile("cp.async.commit_group;");
    };

    auto compute_tile = [&](int kt) {
        const uint32_t abase = sbase + (kt % STAGES) * STAGE_BYTES;
        const uint32_t bbase = abase + B_REL;
#pragma unroll
        for (int ks = 0; ks < 4; ++ks) {
            uint32_t a[4][4];
            uint32_t b[4][4];
            // A: 4 x4-ldmatrix (m16 tiles), rows wm*64+mt*16+(lane&15), chunk ks*2+(lane>>4)
            {
                const int ch = ks * 2 + (lane >> 4);
#pragma unroll
                for (int mt = 0; mt < 4; ++mt) {
                    const int rr = wm * 64 + mt * 16 + (lane & 15);
                    const uint32_t addr = abase + rr * 128 + (((uint32_t)(ch ^ (rr & 7))) << 4);
                    asm volatile("ldmatrix.sync.aligned.m8n8.x4.shared.b16 {%0,%1,%2,%3}, [%4];"
                                 : "=r"(a[mt][0]), "=r"(a[mt][1]), "=r"(a[mt][2]), "=r"(a[mt][3])
                                 : "r"(addr));
                }
            }
            // B: 4 x4-ldmatrix, each covers 2 n8-tiles: rows wn*64+p*16+(lane&7)+((lane>>4)*8),
            // chunk ks*2+((lane>>3)&1)
            {
                const int ch = ks * 2 + ((lane >> 3) & 1);
#pragma unroll
                for (int p = 0; p < 4; ++p) {
                    const int rr = wn * 64 + p * 16 + (lane & 7) + ((lane >> 4) * 8);
                    const uint32_t addr = bbase + rr * 128 + (((uint32_t)(ch ^ (rr & 7))) << 4);
                    asm volatile("ldmatrix.sync.aligned.m8n8.x4.shared.b16 {%0,%1,%2,%3}, [%4];"
                                 : "=r"(b[p][0]), "=r"(b[p][1]), "=r"(b[p][2]), "=r"(b[p][3])
                                 : "r"(addr));
                }
            }
#pragma unroll
            for (int mt = 0; mt < 4; ++mt)
#pragma unroll
                for (int nt = 0; nt < 8; ++nt) {
                    const int p = nt >> 1, h = (nt & 1) * 2;
                    asm volatile("mma.sync.aligned.m16n8k16.row.col.f32.f16.f16.f32 "
                                 "{%0,%1,%2,%3}, {%4,%5,%6,%7}, {%8,%9}, {%0,%1,%2,%3};"
                                 : "+f"(acc[mt][nt][0]), "+f"(acc[mt][nt][1]),
                                   "+f"(acc[mt][nt][2]), "+f"(acc[mt][nt][3])
                                 : "r"(a[mt][0]), "r"(a[mt][1]), "r"(a[mt][2]), "r"(a[mt][3]),
                                   "r"(b[p][h]), "r"(b[p][h + 1]));
                }
        }
    };

    load_tile(0);
    load_tile(1);

    for (int kt = 0; kt < KTILES; ++kt) {
        asm volatile("cp.async.wait_group %0;" :: "n"(1));
        __syncthreads();                 // stage kt ready; all warps done reading stage kt-1
        if (kt + 2 < KTILES) load_tile(kt + 2);
        compute_tile(kt);
    }

    // epilogue
    const float alpha = g_absum * (1.0f / ((float)N_DIM * (float)K_DIM));
    const int row0 = bm + wm * 64 + (lane >> 2);
    const int col0 = bn + wn * 64 + (lane & 3) * 2;
#pragma unroll
    for (int mt = 0; mt < 4; ++mt) {
        float* o0 = out + (size_t)(row0 + mt * 16) * N_DIM + col0;
        float* o1 = o0 + (size_t)8 * N_DIM;
#pragma unroll
        for (int nt = 0; nt < 8; ++nt) {
            *(float2*)(o0 + nt * 8) = make_float2(alpha * acc[mt][nt][0], alpha * acc[mt][nt][1]);
            *(float2*)(o1 + nt * 8) = make_float2(alpha * acc[mt][nt][2], alpha * acc[mt][nt][3]);
        }
    }
}

// ---------------- launch ----------------

extern "C" void kernel_launch(void* const* d_in, const int* in_sizes, int n_in,
                              void* d_out, int out_size) {
    const float* x = (const float*)d_in[0];
    const float* w = (const float*)d_in[1];
    if (n_in >= 2 && in_sizes[0] < in_sizes[1]) {  // defensive: x is the bigger tensor
        const float* t = x; x = w; w = t;
    }
    float* out = (float*)d_out;

    cudaFuncSetAttribute(ternary_gemm_kernel,
                         cudaFuncAttributeMaxDynamicSharedMemorySize, SMEM_TOTAL);

    zero_sum_kernel<<<1, 1>>>();
    abs_sum_kernel<<<2048, 256>>>(w);
    quantize_w_kernel<<<(N_DIM * (size_t)K_DIM / 8) / 256, 256>>>(w);
    convert_x_kernel<<<((size_t)M_DIM * K_DIM / 8) / 256, 256>>>(x);

    dim3 grid(N_DIM / BN, M_DIM / BM);
    ternary_gemm_kernel<<<grid, 256, SMEM_TOTAL>>>(out);
}

// round 6
// speedup vs baseline: 1.8891x; 1.0870x over previous
#include <cuda_runtime.h>
#include <cuda_fp16.h>
#include <cstdint>

#define M_DIM 8192
#define N_DIM 4096
#define K_DIM 4096

#define BM 128
#define BN 128
#define BK 64
#define STAGES 3
#define KTILES (K_DIM / BK)

// per-stage smem: A 128x64 f16 (16KB) + B 128x64 f16 (16KB) = 32KB; 3 stages = 96KB
#define STAGE_BYTES 32768
#define B_REL 16384
#define SMEM_TOTAL (STAGES * STAGE_BYTES)

// Scratch (static device arrays: allowed; cudaMalloc: not)
__device__ __half g_xh[(size_t)M_DIM * K_DIM];   // 64 MB: x in fp16
__device__ __half g_ws[(size_t)N_DIM * K_DIM];   // 32 MB: ternary sign pattern in fp16
__device__ float  g_absum;

// ---------------- prep kernels ----------------

__global__ void zero_sum_kernel() { g_absum = 0.0f; }

__global__ void abs_sum_kernel(const float* __restrict__ w) {
    const int n4 = (N_DIM * K_DIM) / 4;
    float s = 0.f;
    const float4* w4 = (const float4*)w;
    for (int j = blockIdx.x * blockDim.x + threadIdx.x; j < n4; j += gridDim.x * blockDim.x) {
        float4 v = w4[j];
        s += fabsf(v.x) + fabsf(v.y) + fabsf(v.z) + fabsf(v.w);
    }
#pragma unroll
    for (int o = 16; o; o >>= 1) s += __shfl_xor_sync(0xffffffffu, s, o);
    __shared__ float red[8];
    int lane = threadIdx.x & 31, wid = threadIdx.x >> 5;
    if (lane == 0) red[wid] = s;
    __syncthreads();
    if (wid == 0) {
        s = (lane < 8) ? red[lane] : 0.f;
#pragma unroll
        for (int o = 4; o; o >>= 1) s += __shfl_xor_sync(0xffffffffu, s, o);
        if (lane == 0) atomicAdd(&g_absum, s);
    }
}

__global__ void quantize_w_kernel(const float* __restrict__ w) {
    const float t = 0.5f * g_absum * (1.0f / ((float)N_DIM * (float)K_DIM));
    size_t i = ((size_t)blockIdx.x * blockDim.x + threadIdx.x) * 8;
    float4 v0 = *(const float4*)(w + i);
    float4 v1 = *(const float4*)(w + i + 4);
    float f[8] = {v0.x, v0.y, v0.z, v0.w, v1.x, v1.y, v1.z, v1.w};
    __half h[8];
#pragma unroll
    for (int j = 0; j < 8; ++j)
        h[j] = __float2half_rn(f[j] > t ? 1.0f : (f[j] < -t ? -1.0f : 0.0f));
    *(uint4*)(g_ws + i) = *(const uint4*)h;
}

__global__ void convert_x_kernel(const float* __restrict__ x) {
    size_t i = ((size_t)blockIdx.x * blockDim.x + threadIdx.x) * 8;
    float4 v0 = *(const float4*)(x + i);
    float4 v1 = *(const float4*)(x + i + 4);
    float f[8] = {v0.x, v0.y, v0.z, v0.w, v1.x, v1.y, v1.z, v1.w};
    __half h[8];
#pragma unroll
    for (int j = 0; j < 8; ++j) h[j] = __float2half_rn(f[j]);
    *(uint4*)(g_xh + i) = *(const uint4*)h;
}

// ---------------- GEMM ----------------

__device__ __forceinline__ uint32_t smem_u32(const void* p) {
    return (uint32_t)__cvta_generic_to_shared(p);
}

__global__ __launch_bounds__(256, 2) void ternary_gemm_kernel(float* __restrict__ out) {
    extern __shared__ char smem[];
    const uint32_t sbase = smem_u32(smem);

    const int tid  = threadIdx.x;
    const int lane = tid & 31;
    const int warp = tid >> 5;
    const int wm = warp >> 2;          // 2 warps along M (64 rows each)
    const int wn = warp & 3;           // 4 warps along N (32 cols each)
    const int bm = blockIdx.y * BM;
    const int bn = blockIdx.x * BN;

    float acc[4][4][4];
#pragma unroll
    for (int i = 0; i < 4; ++i)
#pragma unroll
        for (int j = 0; j < 4; ++j)
#pragma unroll
            for (int k = 0; k < 4; ++k) acc[i][j][k] = 0.f;

    // cp.async: A 128 rows x 8 16B-chunks = 1024 -> 4/thread; B same (128B rows, xor-8 swizzle)
    auto load_tile = [&](int kt) {
        const uint32_t abase = sbase + (kt % STAGES) * STAGE_BYTES;
        const uint32_t bbase = abase + B_REL;
        const __half* gA = g_xh + (size_t)bm * K_DIM + (size_t)kt * BK;
        const __half* gB = g_ws + (size_t)bn * K_DIM + (size_t)kt * BK;
#pragma unroll
        for (int i = 0; i < 4; ++i) {
            const int idx = tid + i * 256;            // 0..1023
            const int r = idx >> 3;                   // row 0..127
            const int c = idx & 7;
            const uint32_t sw = ((uint32_t)((c ^ r) & 7)) << 4;
            asm volatile("cp.async.cg.shared.global [%0], [%1], 16;"
                         :: "r"(abase + r * 128 + sw),
                            "l"((const char*)(gA + (size_t)r * K_DIM) + c * 16));
            asm volatile("cp.async.cg.shared.global [%0], [%1], 16;"
                         :: "r"(bbase + r * 128 + sw),
                            "l"((const char*)(gB + (size_t)r * K_DIM) + c * 16));
        }
        asm volatile("cp.async.commit_group;");
    };

    auto compute_tile = [&](int kt) {
        const uint32_t abase = sbase + (kt % STAGES) * STAGE_BYTES;
        const uint32_t bbase = abase + B_REL;
#pragma unroll
        for (int ks = 0; ks < 4; ++ks) {
            uint32_t a[4][4];
            uint32_t b[2][4];
            // A: 4 x4-ldmatrix (m16x k16 tiles)
            {
                const int ch = ks * 2 + (lane >> 4);
#pragma unroll
                for (int mt = 0; mt < 4; ++mt) {
                    const int rr = wm * 64 + mt * 16 + (lane & 15);
                    const uint32_t addr = abase + rr * 128 + (((uint32_t)(ch ^ (rr & 7))) << 4);
                    asm volatile("ldmatrix.sync.aligned.m8n8.x4.shared.b16 {%0,%1,%2,%3}, [%4];"
                                 : "=r"(a[mt][0]), "=r"(a[mt][1]), "=r"(a[mt][2]), "=r"(a[mt][3])
                                 : "r"(addr));
                }
            }
            // B: 2 x4-ldmatrix, each covers 2 n8-tiles (16 B-rows x k16)
            {
                const int ch = ks * 2 + ((lane >> 3) & 1);
#pragma unroll
                for (int p = 0; p < 2; ++p) {
                    const int rr = wn * 32 + p * 16 + (lane & 7) + ((lane >> 4) * 8);
                    const uint32_t addr = bbase + rr * 128 + (((uint32_t)(ch ^ (rr & 7))) << 4);
                    asm volatile("ldmatrix.sync.aligned.m8n8.x4.shared.b16 {%0,%1,%2,%3}, [%4];"
                                 : "=r"(b[p][0]), "=r"(b[p][1]), "=r"(b[p][2]), "=r"(b[p][3])
                                 : "r"(addr));
                }
            }
#pragma unroll
            for (int mt = 0; mt < 4; ++mt)
#pragma unroll
                for (int nt = 0; nt < 4; ++nt) {
                    const int p = nt >> 1, h = (nt & 1) * 2;
                    asm volatile("mma.sync.aligned.m16n8k16.row.col.f32.f16.f16.f32 "
                                 "{%0,%1,%2,%3}, {%4,%5,%6,%7}, {%8,%9}, {%0,%1,%2,%3};"
                                 : "+f"(acc[mt][nt][0]), "+f"(acc[mt][nt][1]),
                                   "+f"(acc[mt][nt][2]), "+f"(acc[mt][nt][3])
                                 : "r"(a[mt][0]), "r"(a[mt][1]), "r"(a[mt][2]), "r"(a[mt][3]),
                                   "r"(b[p][h]), "r"(b[p][h + 1]));
                }
        }
    };

    load_tile(0);
    load_tile(1);

    for (int kt = 0; kt < KTILES; ++kt) {
        asm volatile("cp.async.wait_group %0;" :: "n"(1));
        __syncthreads();                 // stage kt ready; all warps done reading stage kt-1
        if (kt + 2 < KTILES) load_tile(kt + 2);
        compute_tile(kt);
    }

    // epilogue
    const float alpha = g_absum * (1.0f / ((float)N_DIM * (float)K_DIM));
    const int row0 = bm + wm * 64 + (lane >> 2);
    const int col0 = bn + wn * 32 + (lane & 3) * 2;
#pragma unroll
    for (int mt = 0; mt < 4; ++mt) {
        float* o0 = out + (size_t)(row0 + mt * 16) * N_DIM + col0;
        float* o1 = o0 + (size_t)8 * N_DIM;
#pragma unroll
        for (int nt = 0; nt < 4; ++nt) {
            *(float2*)(o0 + nt * 8) = make_float2(alpha * acc[mt][nt][0], alpha * acc[mt][nt][1]);
            *(float2*)(o1 + nt * 8) = make_float2(alpha * acc[mt][nt][2], alpha * acc[mt][nt][3]);
        }
    }
}

// ---------------- launch ----------------

extern "C" void kernel_launch(void* const* d_in, const int* in_sizes, int n_in,
                              void* d_out, int out_size) {
    const float* x = (const float*)d_in[0];
    const float* w = (const float*)d_in[1];
    if (n_in >= 2 && in_sizes[0] < in_sizes[1]) {  // defensive: x is the bigger tensor
        const float* t = x; x = w; w = t;
    }
    float* out = (float*)d_out;

    cudaFuncSetAttribute(ternary_gemm_kernel,
                         cudaFuncAttributeMaxDynamicSharedMemorySize, SMEM_TOTAL);

    zero_sum_kernel<<<1, 1>>>();
    abs_sum_kernel<<<2048, 256>>>(w);
    quantize_w_kernel<<<(N_DIM * (size_t)K_DIM / 8) / 256, 256>>>(w);
    convert_x_kernel<<<((size_t)M_DIM * K_DIM / 8) / 256, 256>>>(x);

    dim3 grid(N_DIM / BN, M_DIM / BM);
    ternary_gemm_kernel<<<grid, 256, SMEM_TOTAL>>>(out);
}